// round 3
// baseline (speedup 1.0000x reference)
#include <cuda_runtime.h>
#include <cstdint>

#define GRID_G   180
#define NV       (GRID_G * GRID_G)            // 32400
#define CELLS    (179 * 179)                  // 32041
#define NF_BASE  (2 * CELLS)                  // 64082 faces
#define B0       (3 * CELLS)                  // 96123
#define NUM_NEW  (B0 + 358)                   // 96481
#define DIM      256
#define BATCH    4
#define ROWS_OUT (NV + NUM_NEW)               // 128881
#define NFACES4  (4 * NF_BASE)                // 256328
#define NEDGE    (12 * NF_BASE)               // 768984

#define OUT_FEAT_ELEMS   ((size_t)BATCH * ROWS_OUT * DIM)      // 131,974,144
#define OUT_NF_ELEMS     ((size_t)BATCH * NFACES4 * 3)         // 3,075,936

#define TOTAL4       (BATCH * ROWS_OUT * (DIM / 4))            // 32,993,536 float4 slots
#define SLOTS_PER_T  4
#define FEAT_BLOCKS  ((TOTAL4 + 1023) / 1024)                  // 4 slots/thread, 256 thr
#define TOPO_BPB     ((NF_BASE + 255) / 256)                   // 251 blocks per batch
#define TOPO_BLOCKS  (TOPO_BPB * BATCH)                        // 1004

// Analytic endpoints of the j-th new edge (first-occurrence order).
__device__ __forceinline__ void edge_endpoints(int j, int& p0, int& p1) {
    if (j < B0) {
        int q = j / 3;
        int t = j - q * 3;
        int r = q / 179;
        int cc = q - r * 179;
        int v00 = r * GRID_G + cc;
        if (t == 0)      { p0 = v00;       p1 = v00 + 1;   }      // H(r,cc)
        else if (t == 1) { p0 = v00 + 1;   p1 = v00 + 181; }      // V(r,cc+1)
        else             { p0 = v00;       p1 = v00 + 181; }      // D(r,cc)
    } else {
        int m = j - B0;
        if (m <= 177)      { p0 = m * GRID_G;       p1 = (m + 1) * GRID_G; }     // V(m,0)
        else if (m == 178) { p0 = 179 * GRID_G;     p1 = 179 * GRID_G + 1; }     // H(179,0)
        else if (m == 179) { p0 = 178 * GRID_G;     p1 = 179 * GRID_G;     }     // V(178,0)
        else { int cc = m - 179; p0 = 179 * GRID_G + cc; p1 = p0 + 1; }          // H(179,cc)
    }
}

__device__ __forceinline__ void topo_face(float* __restrict__ out, int f, int b) {
    int v0, v1, v2, n0, n1, n2;
    if (f < CELLS) {
        int c = f;
        int r = c / 179, cc = c - r * 179;
        int v00 = r * GRID_G + cc;
        v0 = v00; v1 = v00 + 1; v2 = v00 + 181;
        n0 = NV + 3 * c;        // H(r,cc)
        n1 = NV + 3 * c + 1;    // V(r,cc+1)
        n2 = NV + 3 * c + 2;    // D(r,cc)
    } else {
        int c = f - CELLS;
        int r = c / 179, cc = c - r * 179;
        int v00 = r * GRID_G + cc;
        v0 = v00; v1 = v00 + 181; v2 = v00 + 180;
        n0 = NV + 3 * c + 2;    // D(r,cc)
        if (r < 178) n1 = NV + 3 * ((r + 1) * 179 + cc);
        else         n1 = (cc == 0) ? (NV + B0 + 178) : (NV + B0 + 179 + cc);
        if (cc >= 1) n2 = NV + 3 * (r * 179 + cc - 1) + 1;
        else         n2 = (r <= 177) ? (NV + B0 + r) : (NV + B0 + 179);
    }

    float* nf  = out + OUT_FEAT_ELEMS + (size_t)b * NFACES4 * 3;
    float* ne0 = out + OUT_FEAT_ELEMS + OUT_NF_ELEMS + (size_t)b * 2 * NEDGE;
    float* ne1 = ne0 + NEDGE;

    int ta[4] = { v0, n0, n1, n0 };
    int tb[4] = { n0, v1, v2, n1 };
    int tc[4] = { n2, n1, n2, n2 };
    int rows[4] = { f, NF_BASE + f, 2 * NF_BASE + f, 3 * NF_BASE + f };

#pragma unroll
    for (int k = 0; k < 4; k++) {
        int g = rows[k];
        float A = (float)ta[k], Bv = (float)tb[k], Cv = (float)tc[k];
        __stcs(&nf[3 * g],     A);
        __stcs(&nf[3 * g + 1], Bv);
        __stcs(&nf[3 * g + 2], Cv);
        __stcs(&ne0[g],               A);
        __stcs(&ne0[4 * NF_BASE + g], Bv);
        __stcs(&ne0[8 * NF_BASE + g], Cv);
        __stcs(&ne1[g],               Bv);
        __stcs(&ne1[4 * NF_BASE + g], Cv);
        __stcs(&ne1[8 * NF_BASE + g], A);
    }
}

// Fused kernel. Feature blocks: 4 float4 slots per thread, ALL loads front-
// batched before any store (max MLP). Copy rows use the degenerate edge
// (p0 == p1); 0.5*(a+a) == a exactly in fp32, so one code path, no branches
// between the loads.
__global__ void __launch_bounds__(256) fused_kernel(const float4* __restrict__ x,
                                                    float* __restrict__ out) {
    if (blockIdx.x < FEAT_BLOCKS) {
        const int per_b = ROWS_OUT * (DIM / 4);          // 8,248,384
        int base = blockIdx.x * 1024 + threadIdx.x;
        float4* out4 = (float4*)out;

        float4 va[SLOTS_PER_T], vb[SLOTS_PER_T];
        int    oidx[SLOTS_PER_T];
        bool   valid[SLOTS_PER_T];

#pragma unroll
        for (int k = 0; k < SLOTS_PER_T; k++) {
            int t = base + k * 256;
            valid[k] = (t < TOTAL4);
            int tt  = valid[k] ? t : 0;
            int b   = tt / per_b;
            int rem = tt - b * per_b;
            int row = rem >> 6;
            int q   = rem & 63;

            int p0, p1;
            if (row < NV) { p0 = row; p1 = row; }
            else          { edge_endpoints(row - NV, p0, p1); }

            const float4* xb = x + (size_t)b * NV * (DIM / 4);
            va[k] = __ldg(&xb[p0 * 64 + q]);
            vb[k] = __ldg(&xb[p1 * 64 + q]);
            oidx[k] = b * per_b + row * 64 + q;
        }

#pragma unroll
        for (int k = 0; k < SLOTS_PER_T; k++) {
            if (valid[k]) {
                float4 r4;
                r4.x = 0.5f * (va[k].x + vb[k].x);
                r4.y = 0.5f * (va[k].y + vb[k].y);
                r4.z = 0.5f * (va[k].z + vb[k].z);
                r4.w = 0.5f * (va[k].w + vb[k].w);
                __stcs(&out4[oidx[k]], r4);
            }
        }
    } else {
        int t = blockIdx.x - FEAT_BLOCKS;
        int b = t / TOPO_BPB;
        int f = (t - b * TOPO_BPB) * 256 + threadIdx.x;
        if (f < NF_BASE) topo_face(out, f, b);
    }
}

extern "C" void kernel_launch(void* const* d_in, const int* in_sizes, int n_in,
                              void* d_out, int out_size) {
    const float4* x = (const float4*)d_in[0];   // x (4, 32400, 256) f32
    float* out = (float*)d_out;
    fused_kernel<<<FEAT_BLOCKS + TOPO_BLOCKS, 256>>>(x, out);
}

// round 4
// speedup vs baseline: 1.0017x; 1.0017x over previous
#include <cuda_runtime.h>
#include <cstdint>

#define GRID_G   180
#define NV       (GRID_G * GRID_G)            // 32400
#define CELLS    (179 * 179)                  // 32041
#define NF_BASE  (2 * CELLS)                  // 64082 faces
#define B0       (3 * CELLS)                  // 96123
#define NUM_NEW  (B0 + 358)                   // 96481
#define DIM      256
#define BATCH    4
#define ROWS_OUT (NV + NUM_NEW)               // 128881
#define NFACES4  (4 * NF_BASE)                // 256328
#define NEDGE    (12 * NF_BASE)               // 768984

#define OUT_FEAT_ELEMS   ((size_t)BATCH * ROWS_OUT * DIM)      // 131,974,144
#define OUT_NF_ELEMS     ((size_t)BATCH * NFACES4 * 3)         // 3,075,936

#define TOTAL4       (BATCH * ROWS_OUT * (DIM / 4))            // 32,993,536 float4 slots
#define FEAT_BLOCKS  ((TOTAL4 + 511) / 512)                    // 2 slots/thread, 256 thr
#define TOPO_BPB     ((NF_BASE + 255) / 256)                   // 251 blocks per batch
#define TOPO_BLOCKS  (TOPO_BPB * BATCH)                        // 1004

// Analytic endpoints of the j-th new edge (first-occurrence order).
__device__ __forceinline__ void edge_endpoints(int j, int& p0, int& p1) {
    if (j < B0) {
        int q = j / 3;
        int t = j - q * 3;
        int r = q / 179;
        int cc = q - r * 179;
        int v00 = r * GRID_G + cc;
        if (t == 0)      { p0 = v00;       p1 = v00 + 1;   }      // H(r,cc)
        else if (t == 1) { p0 = v00 + 1;   p1 = v00 + 181; }      // V(r,cc+1)
        else             { p0 = v00;       p1 = v00 + 181; }      // D(r,cc)
    } else {
        int m = j - B0;
        if (m <= 177)      { p0 = m * GRID_G;       p1 = (m + 1) * GRID_G; }     // V(m,0)
        else if (m == 178) { p0 = 179 * GRID_G;     p1 = 179 * GRID_G + 1; }     // H(179,0)
        else if (m == 179) { p0 = 178 * GRID_G;     p1 = 179 * GRID_G;     }     // V(178,0)
        else { int cc = m - 179; p0 = 179 * GRID_G + cc; p1 = p0 + 1; }          // H(179,cc)
    }
}

__device__ __forceinline__ void feat_slot(const float4* __restrict__ x,
                                          float4* __restrict__ out, int tid) {
    const int per_b = ROWS_OUT * (DIM / 4);             // 8,248,384
    int b   = tid / per_b;
    int rem = tid - b * per_b;
    int row = rem >> 6;
    int q   = rem & 63;

    const float4* xb = x + (size_t)b * NV * (DIM / 4);
    float4*       ob = out + (size_t)b * ROWS_OUT * (DIM / 4);

    if (row < NV) {
        // Pure streaming copy: no reuse -> bypass L1 on the load, evict-first store.
        float4 v = __ldcg(&xb[row * 64 + q]);
        __stcs(&ob[row * 64 + q], v);
    } else {
        int j = row - NV;
        int p0, p1;
        edge_endpoints(j, p0, p1);
        float4 a = __ldg(&xb[p0 * 64 + q]);     // reused across neighboring edges
        float4 c = __ldg(&xb[p1 * 64 + q]);
        float4 r4;
        r4.x = 0.5f * (a.x + c.x);
        r4.y = 0.5f * (a.y + c.y);
        r4.z = 0.5f * (a.z + c.z);
        r4.w = 0.5f * (a.w + c.w);
        __stcs(&ob[row * 64 + q], r4);
    }
}

__device__ __forceinline__ void topo_face(float* __restrict__ out, int f, int b) {
    int v0, v1, v2, n0, n1, n2;
    if (f < CELLS) {
        int c = f;
        int r = c / 179, cc = c - r * 179;
        int v00 = r * GRID_G + cc;
        v0 = v00; v1 = v00 + 1; v2 = v00 + 181;
        n0 = NV + 3 * c;        // H(r,cc)
        n1 = NV + 3 * c + 1;    // V(r,cc+1)
        n2 = NV + 3 * c + 2;    // D(r,cc)
    } else {
        int c = f - CELLS;
        int r = c / 179, cc = c - r * 179;
        int v00 = r * GRID_G + cc;
        v0 = v00; v1 = v00 + 181; v2 = v00 + 180;
        n0 = NV + 3 * c + 2;    // D(r,cc)
        if (r < 178) n1 = NV + 3 * ((r + 1) * 179 + cc);
        else         n1 = (cc == 0) ? (NV + B0 + 178) : (NV + B0 + 179 + cc);
        if (cc >= 1) n2 = NV + 3 * (r * 179 + cc - 1) + 1;
        else         n2 = (r <= 177) ? (NV + B0 + r) : (NV + B0 + 179);
    }

    float* nf  = out + OUT_FEAT_ELEMS + (size_t)b * NFACES4 * 3;
    float* ne0 = out + OUT_FEAT_ELEMS + OUT_NF_ELEMS + (size_t)b * 2 * NEDGE;
    float* ne1 = ne0 + NEDGE;

    int ta[4] = { v0, n0, n1, n0 };
    int tb[4] = { n0, v1, v2, n1 };
    int tc[4] = { n2, n1, n2, n2 };
    int rows[4] = { f, NF_BASE + f, 2 * NF_BASE + f, 3 * NF_BASE + f };

#pragma unroll
    for (int k = 0; k < 4; k++) {
        int g = rows[k];
        float A = (float)ta[k], Bv = (float)tb[k], Cv = (float)tc[k];
        __stcs(&nf[3 * g],     A);
        __stcs(&nf[3 * g + 1], Bv);
        __stcs(&nf[3 * g + 2], Cv);
        __stcs(&ne0[g],               A);
        __stcs(&ne0[4 * NF_BASE + g], Bv);
        __stcs(&ne0[8 * NF_BASE + g], Cv);
        __stcs(&ne1[g],               Bv);
        __stcs(&ne1[4 * NF_BASE + g], Cv);
        __stcs(&ne1[8 * NF_BASE + g], A);
    }
}

// Fused: topo blocks FIRST (their writes overlap feat's first wave), then the
// feature region at 2 float4 slots/thread (low regs -> high occupancy, MLP
// below the L1tex contention knee).
__global__ void __launch_bounds__(256) fused_kernel(const float4* __restrict__ x,
                                                    float* __restrict__ out) {
    if (blockIdx.x < TOPO_BLOCKS) {
        int t = blockIdx.x;
        int b = t / TOPO_BPB;
        int f = (t - b * TOPO_BPB) * 256 + threadIdx.x;
        if (f < NF_BASE) topo_face(out, f, b);
    } else {
        int base = (blockIdx.x - TOPO_BLOCKS) * 512 + threadIdx.x;
        if (base < TOTAL4) feat_slot(x, (float4*)out, base);
        int second = base + 256;
        if (second < TOTAL4) feat_slot(x, (float4*)out, second);
    }
}

extern "C" void kernel_launch(void* const* d_in, const int* in_sizes, int n_in,
                              void* d_out, int out_size) {
    const float4* x = (const float4*)d_in[0];   // x (4, 32400, 256) f32
    float* out = (float*)d_out;
    fused_kernel<<<TOPO_BLOCKS + FEAT_BLOCKS, 256>>>(x, out);
}